// round 10
// baseline (speedup 1.0000x reference)
#include <cuda_runtime.h>
#include <cuda_bf16.h>
#include <cstdint>

#define B_ 16
#define T_ 256
#define H_ 128
#define E_ 128
#define V_ 50000
#define G_ 512          // 4*H
#define M_ 4096         // B*T

typedef unsigned long long ull;

// ---------------- scratch (no cudaMalloc allowed) ----------------
__device__ float g_xp[M_ * G_];
__device__ float g_y0[M_ * H_];
__device__ __nv_bfloat16 g_Whi[(size_t)V_ * H_];
__device__ __nv_bfloat16 g_Wlo[(size_t)V_ * H_];
__device__ __nv_bfloat16 g_Ahi[M_ * H_];
__device__ __nv_bfloat16 g_Alo[M_ * H_];

// ---------------- f32x2 helpers ----------------
__device__ __forceinline__ ull fma2(ull a, ull b, ull c) {
    ull d; asm("fma.rn.f32x2 %0, %1, %2, %3;" : "=l"(d) : "l"(a), "l"(b), "l"(c)); return d;
}
__device__ __forceinline__ ull add2(ull a, ull b) {
    ull d; asm("add.rn.f32x2 %0, %1, %2;" : "=l"(d) : "l"(a), "l"(b)); return d;
}
__device__ __forceinline__ float2 unpack2(ull v) {
    float2 r; asm("mov.b64 {%0, %1}, %2;" : "=f"(r.x), "=f"(r.y) : "l"(v)); return r;
}

// ---------------- Ampere-path tensor helpers (valid on compute_103) --------
__device__ __forceinline__ uint32_t smem_u32(const void* p) {
    uint32_t a;
    asm("{ .reg .u64 t; cvta.to.shared.u64 t, %1; cvt.u32.u64 %0, t; }" : "=r"(a) : "l"(p));
    return a;
}
__device__ __forceinline__ void cpasync16(uint32_t dst, const void* src) {
    asm volatile("cp.async.cg.shared.global [%0], [%1], 16;" :: "r"(dst), "l"(src));
}
#define CP_COMMIT() asm volatile("cp.async.commit_group;" ::: "memory")
#define CP_WAIT(n)  asm volatile("cp.async.wait_group %0;" :: "n"(n) : "memory")

__device__ __forceinline__ void ldsm_x4(uint32_t& r0, uint32_t& r1, uint32_t& r2, uint32_t& r3,
                                        uint32_t addr) {
    asm volatile("ldmatrix.sync.aligned.m8n8.x4.shared.b16 {%0,%1,%2,%3}, [%4];"
                 : "=r"(r0), "=r"(r1), "=r"(r2), "=r"(r3) : "r"(addr));
}
__device__ __forceinline__ void mma_bf16(float* c, const uint32_t* a, const uint32_t* b) {
    asm volatile(
        "mma.sync.aligned.m16n8k16.row.col.f32.bf16.bf16.f32 "
        "{%0,%1,%2,%3}, {%4,%5,%6,%7}, {%8,%9}, {%0,%1,%2,%3};"
        : "+f"(c[0]), "+f"(c[1]), "+f"(c[2]), "+f"(c[3])
        : "r"(a[0]), "r"(a[1]), "r"(a[2]), "r"(a[3]), "r"(b[0]), "r"(b[1]));
}

// ---------------------------------------------------------------------------
// hi/lo bf16 split conversion (vectorized x4) — used for fc_w only now
// ---------------------------------------------------------------------------
__global__ __launch_bounds__(256)
void cvt_hilo(const float4* __restrict__ src, ushort4* __restrict__ hi,
              ushort4* __restrict__ lo, int n4)
{
    int i = blockIdx.x * 256 + threadIdx.x;
    if (i >= n4) return;
    float4 v = src[i];
    ushort4 h, l;
    {
        __nv_bfloat16 hb;
        hb = __float2bfloat16(v.x); h.x = __bfloat16_as_ushort(hb);
        l.x = __bfloat16_as_ushort(__float2bfloat16(v.x - __bfloat162float(hb)));
        hb = __float2bfloat16(v.y); h.y = __bfloat16_as_ushort(hb);
        l.y = __bfloat16_as_ushort(__float2bfloat16(v.y - __bfloat162float(hb)));
        hb = __float2bfloat16(v.z); h.z = __bfloat16_as_ushort(hb);
        l.z = __bfloat16_as_ushort(__float2bfloat16(v.z - __bfloat162float(hb)));
        hb = __float2bfloat16(v.w); h.w = __bfloat16_as_ushort(hb);
        l.w = __bfloat16_as_ushort(__float2bfloat16(v.w - __bfloat162float(hb)));
    }
    hi[i] = h;
    lo[i] = l;
}

// ---------------------------------------------------------------------------
// Projection GEMM: C[M_,512] = A @ W^T + bias   (unchanged)
// ---------------------------------------------------------------------------
template<bool GATHER>
__global__ __launch_bounds__(256)
void proj_kernel(const float* __restrict__ A, const int* __restrict__ xidx,
                 const float* __restrict__ emb, const float* __restrict__ W,
                 const float* __restrict__ bia, const float* __restrict__ bib,
                 float* __restrict__ C)
{
    __shared__ float As[64][64];
    __shared__ float Bs[64][64];
    const int tid = threadIdx.x;
    const int tx = tid & 15, ty = tid >> 4;
    const int m0 = blockIdx.y * 64, n0 = blockIdx.x * 64;
    const int l  = tid & 63;
    const int kq = tid >> 6;

    const float* arow;
    if (GATHER) arow = emb + (size_t)xidx[m0 + l] * E_;
    else        arow = A   + (size_t)(m0 + l) * H_;
    const float* brow = W + (size_t)(n0 + l) * H_;

    float acc[4][4] = {};
    for (int kc = 0; kc < 128; kc += 64) {
        __syncthreads();
        #pragma unroll
        for (int it = 0; it < 4; it++) {
            int kb = kq * 4 + it * 16;
            float4 va = *(const float4*)(arow + kc + kb);
            As[kb+0][l] = va.x; As[kb+1][l] = va.y; As[kb+2][l] = va.z; As[kb+3][l] = va.w;
            float4 vb = *(const float4*)(brow + kc + kb);
            Bs[kb+0][l] = vb.x; Bs[kb+1][l] = vb.y; Bs[kb+2][l] = vb.z; Bs[kb+3][l] = vb.w;
        }
        __syncthreads();
        #pragma unroll 16
        for (int k = 0; k < 64; k++) {
            float4 a4 = *(const float4*)&As[k][ty * 4];
            float4 b4 = *(const float4*)&Bs[k][tx * 4];
            float av[4] = {a4.x, a4.y, a4.z, a4.w};
            float bv[4] = {b4.x, b4.y, b4.z, b4.w};
            #pragma unroll
            for (int i = 0; i < 4; i++)
                #pragma unroll
                for (int j = 0; j < 4; j++)
                    acc[i][j] = fmaf(av[i], bv[j], acc[i][j]);
        }
    }
    #pragma unroll
    for (int i = 0; i < 4; i++) {
        int m = m0 + ty * 4 + i;
        #pragma unroll
        for (int j = 0; j < 4; j++) {
            int n = n0 + tx * 4 + j;
            C[(size_t)m * G_ + n] = acc[i][j] + bia[n] + bib[n];
        }
    }
}

// ---------------------------------------------------------------------------
// LSTM recurrence, 2-CTA cluster per batch element.
// R10: barrier.cluster replaced by an mbarrier handshake:
//   every thread: st.shared::cluster act to peer, then
//   mbarrier.arrive.release.cluster on the PEER's bar[p] (release orders the
//   thread's own store). Consumers (tid<128) try_wait.acquire.cluster on the
//   LOCAL bar[p] (256 arrivals); everyone else is gated by __syncthreads.
// mode==1: fuse bf16 hi/lo split of h into the epilogue (feeds FC directly).
// ---------------------------------------------------------------------------
__global__ __launch_bounds__(256, 1) __cluster_dims__(2, 1, 1)
void lstm_kernel(const float* __restrict__ xp, const float* __restrict__ Whh,
                 float* __restrict__ y, __nv_bfloat16* __restrict__ yhi,
                 __nv_bfloat16* __restrict__ ylo,
                 float* __restrict__ hc_out, int layer, int mode)
{
    __shared__ float h_s[H_];
    __shared__ float act[2][G_];
    __shared__ __align__(8) ull mbar[2];

    const int tid = threadIdx.x;
    uint32_t rank; asm("mov.u32 %0, %%cluster_ctarank;" : "=r"(rank));
    const int b  = blockIdx.x >> 1;
    const int gG = (int)rank * 256 + tid;     // global gate row 0..511
    const int gtype = gG >> 7;                // 0:i 1:f 2:g~ 3:o

    // Full W_hh row in registers (64 ull = 128 f32)
    ull w2[64];
    {
        const ulonglong2* wp = (const ulonglong2*)(Whh + (size_t)gG * H_);
        #pragma unroll
        for (int i = 0; i < 32; i++) { ulonglong2 v = wp[i]; w2[2*i] = v.x; w2[2*i+1] = v.y; }
    }

    // local mbarrier init (count = 256 peer arrivals per phase)
    const uint32_t lb0 = smem_u32(&mbar[0]);
    const uint32_t lb1 = smem_u32(&mbar[1]);
    if (tid == 0) {
        asm volatile("mbarrier.init.shared.b64 [%0], %1;" :: "r"(lb0), "r"(256u) : "memory");
        asm volatile("mbarrier.init.shared.b64 [%0], %1;" :: "r"(lb1), "r"(256u) : "memory");
    }

    // peer addresses: act slots (both parity buffers) + peer barriers
    const uint32_t peer = rank ^ 1u;
    uint32_t ra0, ra1, rb0, rb1;
    {
        uint32_t la0 = smem_u32(&act[0][gG]);
        uint32_t la1 = smem_u32(&act[1][gG]);
        asm("mapa.shared::cluster.u32 %0, %1, %2;" : "=r"(ra0) : "r"(la0), "r"(peer));
        asm("mapa.shared::cluster.u32 %0, %1, %2;" : "=r"(ra1) : "r"(la1), "r"(peer));
        asm("mapa.shared::cluster.u32 %0, %1, %2;" : "=r"(rb0) : "r"(lb0), "r"(peer));
        asm("mapa.shared::cluster.u32 %0, %1, %2;" : "=r"(rb1) : "r"(lb1), "r"(peer));
    }

    float c = 0.f;
    if (tid < H_) h_s[tid] = 0.f;
    __syncthreads();
    // both CTAs' mbarriers must be initialized before any peer arrive
    asm volatile("barrier.cluster.arrive.aligned;" ::: "memory");
    asm volatile("barrier.cluster.wait.aligned;"   ::: "memory");

    const float* xpb = xp + (size_t)b * T_ * G_ + gG;

    int ph0 = 0, ph1 = 0;                    // phase parity per barrier

    for (int t = 0; t < T_; t++) {
        float xv = __ldg(xpb + (size_t)t * G_);   // issued early, used late

        // dot: h_s (broadcast LDS) x W-row (registers), 4 independent chains
        ull a0 = 0, a1 = 0, a2 = 0, a3 = 0;
        const ulonglong2* hp = (const ulonglong2*)h_s;
        #pragma unroll
        for (int i = 0; i < 32; i++) {
            ulonglong2 hv = hp[i];
            if (i & 1) { a2 = fma2(w2[2*i], hv.x, a2); a3 = fma2(w2[2*i+1], hv.y, a3); }
            else       { a0 = fma2(w2[2*i], hv.x, a0); a1 = fma2(w2[2*i+1], hv.y, a1); }
        }
        a0 = add2(a0, a2); a1 = add2(a1, a3); a0 = add2(a0, a1);
        float2 pr = unpack2(a0);
        float raw = pr.x + pr.y + xv;

        float a = (gtype == 2) ? tanhf(raw) : (1.0f / (1.0f + __expf(-raw)));

        const int p = t & 1;
        act[p][gG] = a;                               // local copy
        asm volatile("st.shared::cluster.f32 [%0], %1;"
                     :: "r"(p ? ra1 : ra0), "f"(a));  // peer copy
        // release-arrive on the PEER's barrier: orders this thread's store
        asm volatile("mbarrier.arrive.release.cluster.shared::cluster.b64 _, [%0];"
                     :: "r"(p ? rb1 : rb0) : "memory");

        if (tid < H_) {
            // wait for all 256 peer arrivals (acquire, cluster scope)
            const uint32_t lb = p ? lb1 : lb0;
            const uint32_t pa = (uint32_t)(p ? ph1 : ph0);
            uint32_t done;
            asm volatile(
                "{\n\t.reg .pred q;\n\t"
                "mbarrier.try_wait.parity.acquire.cluster.shared::cta.b64 q, [%1], %2;\n\t"
                "selp.b32 %0, 1, 0, q;\n\t}"
                : "=r"(done) : "r"(lb), "r"(pa) : "memory");
            if (!done) {
                asm volatile(
                    "{\n\t.reg .pred Q;\n\t"
                    "LW_%=:\n\t"
                    "mbarrier.try_wait.parity.acquire.cluster.shared::cta.b64 Q, [%0], %1, 0x989680;\n\t"
                    "@Q bra.uni LD_%=;\n\t"
                    "bra.uni LW_%=;\n\t"
                    "LD_%=:\n\t}"
                    :: "r"(lb), "r"(pa) : "memory");
            }

            float iv = act[p][tid];
            float fv = act[p][H_ + tid];
            float gv = act[p][2 * H_ + tid];
            float ov = act[p][3 * H_ + tid];
            c = fv * c + iv * gv;
            float hnew = ov * tanhf(c);
            h_s[tid] = hnew;
            if (rank == 0) {
                const size_t row = (size_t)b * T_ + t;
                if (mode == 0) {
                    y[row * H_ + tid] = hnew;
                } else {
                    __nv_bfloat16 hb = __float2bfloat16(hnew);
                    yhi[row * H_ + tid] = hb;
                    ylo[row * H_ + tid] = __float2bfloat16(hnew - __bfloat162float(hb));
                }
            }
        }
        if (p) ph1 ^= 1; else ph0 ^= 1;
        __syncthreads();                              // h_s ready for next dot
    }

    if (rank == 0 && tid < H_) {
        hc_out[(size_t)layer * (B_ * H_) + b * H_ + tid]       = h_s[tid];
        hc_out[(size_t)(2 + layer) * (B_ * H_) + b * H_ + tid] = c;
    }
    // no CTA may exit while the peer could still address its SMEM
    asm volatile("barrier.cluster.arrive.aligned;" ::: "memory");
    asm volatile("barrier.cluster.wait.aligned;"   ::: "memory");
}

// ---------------------------------------------------------------------------
// FC head via mma.sync (HMMA): logits = y1 @ fc_w^T + fc_b
// hi/lo bf16 split: acc = Ahi*Whi + Ahi*Wlo + Alo*Whi  (virtual K = 384)
// A tiles resident (4 x 18432), B double-buffered (2 x 18432). 110592 B smem.
// ---------------------------------------------------------------------------
#define FC_PAD    72                        // row stride in bf16 elems
#define FC_TILE   (128 * FC_PAD * 2)        // 18432 bytes per 128x64 tile
#define FC_BBASE  (4 * FC_TILE)             // B region offset
#define FC_SMEM   (FC_BBASE + 2 * FC_TILE)  // 110592

__device__ __forceinline__ void fc_load_A(uint32_t dst,
    const __nv_bfloat16* __restrict__ src, int m0, int koff, int tid)
{
    #pragma unroll
    for (int it = 0; it < 4; it++) {
        int idx = tid + it * 256;
        int row = idx >> 3, c8 = idx & 7;
        cpasync16(dst + (uint32_t)(row * FC_PAD + c8 * 8) * 2,
                  src + (size_t)(m0 + row) * H_ + koff + c8 * 8);
    }
}
__device__ __forceinline__ void fc_load_B(uint32_t dst,
    const __nv_bfloat16* __restrict__ src, int n0, int koff, int tid)
{
    #pragma unroll
    for (int it = 0; it < 4; it++) {
        int idx = tid + it * 256;
        int row = idx >> 3, c8 = idx & 7;
        int gn = n0 + row; if (gn >= V_) gn = V_ - 1;   // clamp; never stored
        cpasync16(dst + (uint32_t)(row * FC_PAD + c8 * 8) * 2,
                  src + (size_t)gn * H_ + koff + c8 * 8);
    }
}

__global__ __launch_bounds__(256, 2)
void fc_mma_kernel(const __nv_bfloat16* __restrict__ Ahi, const __nv_bfloat16* __restrict__ Alo,
                   const __nv_bfloat16* __restrict__ Whi, const __nv_bfloat16* __restrict__ Wlo,
                   const float* __restrict__ fcb, float* __restrict__ C)
{
    extern __shared__ char smem[];
    const uint32_t sbase = smem_u32(smem);
    const int tid  = threadIdx.x;
    const int wid  = tid >> 5, lane = tid & 31;
    const int wm   = wid >> 2;
    const int wn   = wid & 3;
    const int n0   = blockIdx.x * 128;
    const int m0   = blockIdx.y * 128;

    const uint32_t aRel = (uint32_t)(((wm * 64 + (lane & 15)) * FC_PAD + (lane >> 4) * 8) * 2);
    const uint32_t bRel = (uint32_t)(
        ((wn * 32 + (lane >> 4) * 8 + (lane & 7)) * FC_PAD + ((lane >> 3) & 1) * 8) * 2);

    float acc[4][4][4];
    #pragma unroll
    for (int i = 0; i < 4; i++)
        #pragma unroll
        for (int j = 0; j < 4; j++)
            #pragma unroll
            for (int k = 0; k < 4; k++) acc[i][j][k] = 0.f;

    fc_load_A(sbase + 0 * FC_TILE, Ahi, m0, 0,  tid);
    fc_load_A(sbase + 1 * FC_TILE, Ahi, m0, 64, tid);
    fc_load_A(sbase + 2 * FC_TILE, Alo, m0, 0,  tid);
    fc_load_A(sbase + 3 * FC_TILE, Alo, m0, 64, tid);
    fc_load_B(sbase + FC_BBASE + 0 * FC_TILE, Whi, n0, 0, tid);
    CP_COMMIT();                                        // G0 = {A x4, B0}
    fc_load_B(sbase + FC_BBASE + 1 * FC_TILE, Whi, n0, 64, tid);
    CP_COMMIT();                                        // G1 = {B1}

    #pragma unroll
    for (int c = 0; c < 6; c++) {
        const int At[6] = {0, 1, 0, 1, 2, 3};
        if (c < 5) { CP_WAIT(1); } else { CP_WAIT(0); }
        __syncthreads();

        const uint32_t aB = sbase + (uint32_t)At[c] * FC_TILE + aRel;
        const uint32_t bB = sbase + FC_BBASE + (uint32_t)(c & 1) * FC_TILE + bRel;
        #pragma unroll
        for (int k16 = 0; k16 < 4; k16++) {
            uint32_t a[4][4], b[4][2];
            #pragma unroll
            for (int mf = 0; mf < 4; mf++)
                ldsm_x4(a[mf][0], a[mf][1], a[mf][2], a[mf][3],
                        aB + mf * (16 * FC_PAD * 2) + k16 * 32);
            #pragma unroll
            for (int np = 0; np < 2; np++)
                ldsm_x4(b[2*np][0], b[2*np][1], b[2*np+1][0], b[2*np+1][1],
                        bB + np * (16 * FC_PAD * 2) + k16 * 32);
            #pragma unroll
            for (int mf = 0; mf < 4; mf++)
                #pragma unroll
                for (int nf = 0; nf < 4; nf++)
                    mma_bf16(acc[mf][nf], a[mf], b[nf]);
        }
        __syncthreads();

        if (c + 2 <= 5) {
            const __nv_bfloat16* Bp = (c + 2 == 2 || c + 2 == 3) ? Wlo : Whi;
            const int Bk = ((c + 2) & 1) * 64;
            fc_load_B(sbase + FC_BBASE + (uint32_t)(c & 1) * FC_TILE, Bp, n0, Bk, tid);
            CP_COMMIT();
        }
    }

    const int ncol = 2 * (lane & 3);
    const size_t rbase = (size_t)(m0 + wm * 64 + (lane >> 2));
    #pragma unroll
    for (int nf = 0; nf < 4; nf++) {
        const int n = n0 + wn * 32 + nf * 8 + ncol;
        if (n >= V_) continue;
        const float2 bv = *(const float2*)(fcb + n);
        #pragma unroll
        for (int mf = 0; mf < 4; mf++) {
            float* cp = C + (rbase + (size_t)mf * 16) * V_ + n;
            float2 o0 = make_float2(acc[mf][nf][0] + bv.x, acc[mf][nf][1] + bv.y);
            float2 o1 = make_float2(acc[mf][nf][2] + bv.x, acc[mf][nf][3] + bv.y);
            *(float2*)cp                    = o0;
            *(float2*)(cp + (size_t)8 * V_) = o1;
        }
    }
}

// ---------------------------------------------------------------------------
extern "C" void kernel_launch(void* const* d_in, const int* in_sizes, int n_in,
                              void* d_out, int out_size)
{
    const int*   x     = (const int*)  d_in[0];
    const float* emb   = (const float*)d_in[1];
    const float* W_ih0 = (const float*)d_in[2];
    const float* W_hh0 = (const float*)d_in[3];
    const float* b_ih0 = (const float*)d_in[4];
    const float* b_hh0 = (const float*)d_in[5];
    const float* W_ih1 = (const float*)d_in[6];
    const float* W_hh1 = (const float*)d_in[7];
    const float* b_ih1 = (const float*)d_in[8];
    const float* b_hh1 = (const float*)d_in[9];
    const float* fc_w  = (const float*)d_in[10];
    const float* fc_b  = (const float*)d_in[11];
    float* out = (float*)d_out;

    float *xp, *y0;
    __nv_bfloat16 *Whi, *Wlo, *Ahi, *Alo;
    cudaGetSymbolAddress((void**)&xp, g_xp);
    cudaGetSymbolAddress((void**)&y0, g_y0);
    cudaGetSymbolAddress((void**)&Whi, g_Whi);
    cudaGetSymbolAddress((void**)&Wlo, g_Wlo);
    cudaGetSymbolAddress((void**)&Ahi, g_Ahi);
    cudaGetSymbolAddress((void**)&Alo, g_Alo);

    cudaFuncSetAttribute(fc_mma_kernel, cudaFuncAttributeMaxDynamicSharedMemorySize, FC_SMEM);

    float* hc = out + (size_t)M_ * V_;   // logits, then h[2,B,H], c[2,B,H]

    // convert fc_w to bf16 hi/lo
    {
        int n4 = (V_ * H_) / 4;
        cvt_hilo<<<(n4 + 255) / 256, 256>>>((const float4*)fc_w, (ushort4*)Whi, (ushort4*)Wlo, n4);
    }

    // Layer 0 (writes y0 as float)
    proj_kernel<true><<<dim3(G_/64, M_/64), 256>>>(nullptr, x, emb, W_ih0, b_ih0, b_hh0, xp);
    lstm_kernel<<<2 * B_, 256>>>(xp, W_hh0, y0, nullptr, nullptr, hc, 0, 0);

    // Layer 1 (writes Ahi/Alo directly — hi/lo split fused into epilogue)
    proj_kernel<false><<<dim3(G_/64, M_/64), 256>>>(y0, nullptr, nullptr, W_ih1, b_ih1, b_hh1, xp);
    lstm_kernel<<<2 * B_, 256>>>(xp, W_hh1, nullptr, Ahi, Alo, hc, 1, 1);

    // Vocab projection on tensor cores (HMMA via mma.sync)
    fc_mma_kernel<<<dim3((V_ + 127) / 128, M_ / 128), 256, FC_SMEM>>>(Ahi, Alo, Whi, Wlo, fc_b, out);
}

// round 11
// speedup vs baseline: 1.0553x; 1.0553x over previous
#include <cuda_runtime.h>
#include <cuda_bf16.h>
#include <cstdint>

#define B_ 16
#define T_ 256
#define H_ 128
#define E_ 128
#define V_ 50000
#define G_ 512          // 4*H
#define M_ 4096         // B*T

typedef unsigned long long ull;

// ---------------- scratch (no cudaMalloc allowed) ----------------
__device__ float g_xp[M_ * G_];
__device__ float g_y0[M_ * H_];
__device__ __nv_bfloat16 g_Whi[(size_t)V_ * H_];
__device__ __nv_bfloat16 g_Wlo[(size_t)V_ * H_];
__device__ __nv_bfloat16 g_Ahi[M_ * H_];
__device__ __nv_bfloat16 g_Alo[M_ * H_];

// ---------------- f32x2 helpers ----------------
__device__ __forceinline__ ull fma2(ull a, ull b, ull c) {
    ull d; asm("fma.rn.f32x2 %0, %1, %2, %3;" : "=l"(d) : "l"(a), "l"(b), "l"(c)); return d;
}
__device__ __forceinline__ ull add2(ull a, ull b) {
    ull d; asm("add.rn.f32x2 %0, %1, %2;" : "=l"(d) : "l"(a), "l"(b)); return d;
}
__device__ __forceinline__ float2 unpack2(ull v) {
    float2 r; asm("mov.b64 {%0, %1}, %2;" : "=f"(r.x), "=f"(r.y) : "l"(v)); return r;
}

// ---------------- Ampere-path tensor helpers (valid on compute_103) --------
__device__ __forceinline__ uint32_t smem_u32(const void* p) {
    uint32_t a;
    asm("{ .reg .u64 t; cvta.to.shared.u64 t, %1; cvt.u32.u64 %0, t; }" : "=r"(a) : "l"(p));
    return a;
}
__device__ __forceinline__ void cpasync16(uint32_t dst, const void* src) {
    asm volatile("cp.async.cg.shared.global [%0], [%1], 16;" :: "r"(dst), "l"(src));
}
#define CP_COMMIT() asm volatile("cp.async.commit_group;" ::: "memory")
#define CP_WAIT(n)  asm volatile("cp.async.wait_group %0;" :: "n"(n) : "memory")

__device__ __forceinline__ void ldsm_x4(uint32_t& r0, uint32_t& r1, uint32_t& r2, uint32_t& r3,
                                        uint32_t addr) {
    asm volatile("ldmatrix.sync.aligned.m8n8.x4.shared.b16 {%0,%1,%2,%3}, [%4];"
                 : "=r"(r0), "=r"(r1), "=r"(r2), "=r"(r3) : "r"(addr));
}
__device__ __forceinline__ void mma_bf16(float* c, const uint32_t* a, const uint32_t* b) {
    asm volatile(
        "mma.sync.aligned.m16n8k16.row.col.f32.bf16.bf16.f32 "
        "{%0,%1,%2,%3}, {%4,%5,%6,%7}, {%8,%9}, {%0,%1,%2,%3};"
        : "+f"(c[0]), "+f"(c[1]), "+f"(c[2]), "+f"(c[3])
        : "r"(a[0]), "r"(a[1]), "r"(a[2]), "r"(a[3]), "r"(b[0]), "r"(b[1]));
}

// ---------------------------------------------------------------------------
// hi/lo bf16 split conversion (vectorized x4) — fc_w only
// ---------------------------------------------------------------------------
__global__ __launch_bounds__(256)
void cvt_hilo(const float4* __restrict__ src, ushort4* __restrict__ hi,
              ushort4* __restrict__ lo, int n4)
{
    int i = blockIdx.x * 256 + threadIdx.x;
    if (i >= n4) return;
    float4 v = src[i];
    ushort4 h, l;
    {
        __nv_bfloat16 hb;
        hb = __float2bfloat16(v.x); h.x = __bfloat16_as_ushort(hb);
        l.x = __bfloat16_as_ushort(__float2bfloat16(v.x - __bfloat162float(hb)));
        hb = __float2bfloat16(v.y); h.y = __bfloat16_as_ushort(hb);
        l.y = __bfloat16_as_ushort(__float2bfloat16(v.y - __bfloat162float(hb)));
        hb = __float2bfloat16(v.z); h.z = __bfloat16_as_ushort(hb);
        l.z = __bfloat16_as_ushort(__float2bfloat16(v.z - __bfloat162float(hb)));
        hb = __float2bfloat16(v.w); h.w = __bfloat16_as_ushort(hb);
        l.w = __bfloat16_as_ushort(__float2bfloat16(v.w - __bfloat162float(hb)));
    }
    hi[i] = h;
    lo[i] = l;
}

// ---------------------------------------------------------------------------
// Projection GEMM: C[M_,512] = A @ W^T + bias   (unchanged)
// ---------------------------------------------------------------------------
template<bool GATHER>
__global__ __launch_bounds__(256)
void proj_kernel(const float* __restrict__ A, const int* __restrict__ xidx,
                 const float* __restrict__ emb, const float* __restrict__ W,
                 const float* __restrict__ bia, const float* __restrict__ bib,
                 float* __restrict__ C)
{
    __shared__ float As[64][64];
    __shared__ float Bs[64][64];
    const int tid = threadIdx.x;
    const int tx = tid & 15, ty = tid >> 4;
    const int m0 = blockIdx.y * 64, n0 = blockIdx.x * 64;
    const int l  = tid & 63;
    const int kq = tid >> 6;

    const float* arow;
    if (GATHER) arow = emb + (size_t)xidx[m0 + l] * E_;
    else        arow = A   + (size_t)(m0 + l) * H_;
    const float* brow = W + (size_t)(n0 + l) * H_;

    float acc[4][4] = {};
    for (int kc = 0; kc < 128; kc += 64) {
        __syncthreads();
        #pragma unroll
        for (int it = 0; it < 4; it++) {
            int kb = kq * 4 + it * 16;
            float4 va = *(const float4*)(arow + kc + kb);
            As[kb+0][l] = va.x; As[kb+1][l] = va.y; As[kb+2][l] = va.z; As[kb+3][l] = va.w;
            float4 vb = *(const float4*)(brow + kc + kb);
            Bs[kb+0][l] = vb.x; Bs[kb+1][l] = vb.y; Bs[kb+2][l] = vb.z; Bs[kb+3][l] = vb.w;
        }
        __syncthreads();
        #pragma unroll 16
        for (int k = 0; k < 64; k++) {
            float4 a4 = *(const float4*)&As[k][ty * 4];
            float4 b4 = *(const float4*)&Bs[k][tx * 4];
            float av[4] = {a4.x, a4.y, a4.z, a4.w};
            float bv[4] = {b4.x, b4.y, b4.z, b4.w};
            #pragma unroll
            for (int i = 0; i < 4; i++)
                #pragma unroll
                for (int j = 0; j < 4; j++)
                    acc[i][j] = fmaf(av[i], bv[j], acc[i][j]);
        }
    }
    #pragma unroll
    for (int i = 0; i < 4; i++) {
        int m = m0 + ty * 4 + i;
        #pragma unroll
        for (int j = 0; j < 4; j++) {
            int n = n0 + tx * 4 + j;
            C[(size_t)m * G_ + n] = acc[i][j] + bia[n] + bib[n];
        }
    }
}

// ---------------------------------------------------------------------------
// LSTM recurrence, 2-CTA cluster per batch element (R9 proven design:
// barrier.cluster handshake; R10's mbarrier variant regressed and is reverted).
// Each thread holds its full W_hh row (128 floats) in registers.
// mode==1: fuse bf16 hi/lo split of h into the epilogue (feeds FC directly).
// ---------------------------------------------------------------------------
__global__ __launch_bounds__(256, 1) __cluster_dims__(2, 1, 1)
void lstm_kernel(const float* __restrict__ xp, const float* __restrict__ Whh,
                 float* __restrict__ y, __nv_bfloat16* __restrict__ yhi,
                 __nv_bfloat16* __restrict__ ylo,
                 float* __restrict__ hc_out, int layer, int mode)
{
    __shared__ float h_s[H_];
    __shared__ float act[2][G_];

    const int tid = threadIdx.x;
    uint32_t rank; asm("mov.u32 %0, %%cluster_ctarank;" : "=r"(rank));
    const int b  = blockIdx.x >> 1;
    const int gG = (int)rank * 256 + tid;     // global gate row 0..511
    const int gtype = gG >> 7;                // 0:i 1:f 2:g~ 3:o

    // Full W_hh row in registers (64 ull = 128 f32)
    ull w2[64];
    {
        const ulonglong2* wp = (const ulonglong2*)(Whh + (size_t)gG * H_);
        #pragma unroll
        for (int i = 0; i < 32; i++) { ulonglong2 v = wp[i]; w2[2*i] = v.x; w2[2*i+1] = v.y; }
    }

    // peer addresses for this thread's act slot (both parity buffers)
    const uint32_t peer = rank ^ 1u;
    uint32_t ra0, ra1;
    {
        uint32_t la0 = smem_u32(&act[0][gG]);
        uint32_t la1 = smem_u32(&act[1][gG]);
        asm("mapa.shared::cluster.u32 %0, %1, %2;" : "=r"(ra0) : "r"(la0), "r"(peer));
        asm("mapa.shared::cluster.u32 %0, %1, %2;" : "=r"(ra1) : "r"(la1), "r"(peer));
    }

    float c = 0.f;
    if (tid < H_) h_s[tid] = 0.f;
    __syncthreads();                          // h_s init (local readers only)

    const float* xpb = xp + (size_t)b * T_ * G_ + gG;

    for (int t = 0; t < T_; t++) {
        float xv = __ldg(xpb + (size_t)t * G_);   // issued early, used late

        // dot: h_s (broadcast LDS) x W-row (registers), 4 independent chains
        ull a0 = 0, a1 = 0, a2 = 0, a3 = 0;
        const ulonglong2* hp = (const ulonglong2*)h_s;
        #pragma unroll
        for (int i = 0; i < 32; i++) {
            ulonglong2 hv = hp[i];
            if (i & 1) { a2 = fma2(w2[2*i], hv.x, a2); a3 = fma2(w2[2*i+1], hv.y, a3); }
            else       { a0 = fma2(w2[2*i], hv.x, a0); a1 = fma2(w2[2*i+1], hv.y, a1); }
        }
        a0 = add2(a0, a2); a1 = add2(a1, a3); a0 = add2(a0, a1);
        float2 pr = unpack2(a0);
        float raw = pr.x + pr.y + xv;

        float a = (gtype == 2) ? tanhf(raw) : (1.0f / (1.0f + __expf(-raw)));

        const int p = t & 1;
        act[p][gG] = a;                               // local copy
        asm volatile("st.shared::cluster.f32 [%0], %1;"
                     :: "r"(p ? ra1 : ra0), "f"(a));  // peer copy

        asm volatile("barrier.cluster.arrive.aligned;" ::: "memory");
        asm volatile("barrier.cluster.wait.aligned;"   ::: "memory");

        if (tid < H_) {                               // redundant in both CTAs
            float iv = act[p][tid];
            float fv = act[p][H_ + tid];
            float gv = act[p][2 * H_ + tid];
            float ov = act[p][3 * H_ + tid];
            c = fv * c + iv * gv;
            float hnew = ov * tanhf(c);
            h_s[tid] = hnew;
            if (rank == 0) {
                const size_t row = (size_t)b * T_ + t;
                if (mode == 0) {
                    y[row * H_ + tid] = hnew;
                } else {
                    __nv_bfloat16 hb = __float2bfloat16(hnew);
                    yhi[row * H_ + tid] = hb;
                    ylo[row * H_ + tid] = __float2bfloat16(hnew - __bfloat162float(hb));
                }
            }
        }
        __syncthreads();                              // h_s ready for next dot
    }

    if (rank == 0 && tid < H_) {
        hc_out[(size_t)layer * (B_ * H_) + b * H_ + tid]       = h_s[tid];
        hc_out[(size_t)(2 + layer) * (B_ * H_) + b * H_ + tid] = c;
    }
}

// ---------------------------------------------------------------------------
// FC head via mma.sync (HMMA): logits = y1 @ fc_w^T + fc_b
// hi/lo bf16 split: acc = Ahi*Whi + Ahi*Wlo + Alo*Whi  (virtual K = 384)
// R11: B-step reordering. A tiles resident (4). The 6 (A,B) chunk products
// are grouped by B tile so each loaded B is consumed by ALL A tiles needing
// it -> only 4 B loads (was 6), 4 sync pairs (was 6):
//   step0: B=Whi k0  x {A0=Ahi k0,  A2=Alo k0 }
//   step1: B=Whi k64 x {A1=Ahi k64, A3=Alo k64}
//   step2: B=Wlo k0  x {A0}
//   step3: B=Wlo k64 x {A1}
// smem: 4*18432 (A) + 2*18432 (B stages) = 110592 -> 2 CTAs/SM.
// ---------------------------------------------------------------------------
#define FC_PAD    72                        // row stride in bf16 elems
#define FC_TILE   (128 * FC_PAD * 2)        // 18432 bytes per 128x64 tile
#define FC_BBASE  (4 * FC_TILE)             // B region offset
#define FC_SMEM   (FC_BBASE + 2 * FC_TILE)  // 110592

__device__ __forceinline__ void fc_load_A(uint32_t dst,
    const __nv_bfloat16* __restrict__ src, int m0, int koff, int tid)
{
    #pragma unroll
    for (int it = 0; it < 4; it++) {
        int idx = tid + it * 256;
        int row = idx >> 3, c8 = idx & 7;
        cpasync16(dst + (uint32_t)(row * FC_PAD + c8 * 8) * 2,
                  src + (size_t)(m0 + row) * H_ + koff + c8 * 8);
    }
}
__device__ __forceinline__ void fc_load_B(uint32_t dst,
    const __nv_bfloat16* __restrict__ src, int n0, int koff, int tid)
{
    #pragma unroll
    for (int it = 0; it < 4; it++) {
        int idx = tid + it * 256;
        int row = idx >> 3, c8 = idx & 7;
        int gn = n0 + row; if (gn >= V_) gn = V_ - 1;   // clamp; never stored
        cpasync16(dst + (uint32_t)(row * FC_PAD + c8 * 8) * 2,
                  src + (size_t)gn * H_ + koff + c8 * 8);
    }
}

__global__ __launch_bounds__(256, 2)
void fc_mma_kernel(const __nv_bfloat16* __restrict__ Ahi, const __nv_bfloat16* __restrict__ Alo,
                   const __nv_bfloat16* __restrict__ Whi, const __nv_bfloat16* __restrict__ Wlo,
                   const float* __restrict__ fcb, float* __restrict__ C)
{
    extern __shared__ char smem[];
    const uint32_t sbase = smem_u32(smem);
    const int tid  = threadIdx.x;
    const int wid  = tid >> 5, lane = tid & 31;
    const int wm   = wid >> 2;
    const int wn   = wid & 3;
    const int n0   = blockIdx.x * 128;
    const int m0   = blockIdx.y * 128;

    const uint32_t aRel = (uint32_t)(((wm * 64 + (lane & 15)) * FC_PAD + (lane >> 4) * 8) * 2);
    const uint32_t bRel = (uint32_t)(
        ((wn * 32 + (lane >> 4) * 8 + (lane & 7)) * FC_PAD + ((lane >> 3) & 1) * 8) * 2);

    float acc[4][4][4];
    #pragma unroll
    for (int i = 0; i < 4; i++)
        #pragma unroll
        for (int j = 0; j < 4; j++)
            #pragma unroll
            for (int k = 0; k < 4; k++) acc[i][j][k] = 0.f;

    // prologue: resident A tiles + first two B tiles
    fc_load_A(sbase + 0 * FC_TILE, Ahi, m0, 0,  tid);
    fc_load_A(sbase + 1 * FC_TILE, Ahi, m0, 64, tid);
    fc_load_A(sbase + 2 * FC_TILE, Alo, m0, 0,  tid);
    fc_load_A(sbase + 3 * FC_TILE, Alo, m0, 64, tid);
    fc_load_B(sbase + FC_BBASE + 0 * FC_TILE, Whi, n0, 0, tid);
    CP_COMMIT();                                        // G0 = {A x4, B0}
    fc_load_B(sbase + FC_BBASE + 1 * FC_TILE, Whi, n0, 64, tid);
    CP_COMMIT();                                        // G1 = {B1}

    // B-steps: per step, one B tile vs 1-2 A tiles
    #pragma unroll
    for (int s = 0; s < 4; s++) {
        // A tiles per step: {0,2}, {1,3}, {0,-}, {1,-}
        const int At0[4] = {0, 1, 0, 1};
        const int At1[4] = {2, 3, -1, -1};
        if (s < 3) { CP_WAIT(1); } else { CP_WAIT(0); }
        __syncthreads();

        const uint32_t bB = sbase + FC_BBASE + (uint32_t)(s & 1) * FC_TILE + bRel;
        #pragma unroll
        for (int k16 = 0; k16 < 4; k16++) {
            uint32_t b[4][2];
            #pragma unroll
            for (int np = 0; np < 2; np++)
                ldsm_x4(b[2*np][0], b[2*np][1], b[2*np+1][0], b[2*np+1][1],
                        bB + np * (16 * FC_PAD * 2) + k16 * 32);
            {   // first A tile
                const uint32_t aB = sbase + (uint32_t)At0[s] * FC_TILE + aRel;
                uint32_t a[4][4];
                #pragma unroll
                for (int mf = 0; mf < 4; mf++)
                    ldsm_x4(a[mf][0], a[mf][1], a[mf][2], a[mf][3],
                            aB + mf * (16 * FC_PAD * 2) + k16 * 32);
                #pragma unroll
                for (int mf = 0; mf < 4; mf++)
                    #pragma unroll
                    for (int nf = 0; nf < 4; nf++)
                        mma_bf16(acc[mf][nf], a[mf], b[nf]);
            }
            if (s < 2) {  // second A tile (steps 0,1 only)
                const uint32_t aB = sbase + (uint32_t)At1[s] * FC_TILE + aRel;
                uint32_t a[4][4];
                #pragma unroll
                for (int mf = 0; mf < 4; mf++)
                    ldsm_x4(a[mf][0], a[mf][1], a[mf][2], a[mf][3],
                            aB + mf * (16 * FC_PAD * 2) + k16 * 32);
                #pragma unroll
                for (int mf = 0; mf < 4; mf++)
                    #pragma unroll
                    for (int nf = 0; nf < 4; nf++)
                        mma_bf16(acc[mf][nf], a[mf], b[nf]);
            }
        }
        __syncthreads();                    // B stage (s&1) free for reuse

        if (s + 2 <= 3) {                   // prefetch B(s+2) into stage s&1
            const int Bk = (s & 1) * 64;    // steps 2,3 use Wlo k0 / k64
            fc_load_B(sbase + FC_BBASE + (uint32_t)(s & 1) * FC_TILE, Wlo, n0, Bk, tid);
            CP_COMMIT();
        }
    }

    // epilogue: bias + store (mapping verified since R8; n even, V_ even)
    const int ncol = 2 * (lane & 3);
    const size_t rbase = (size_t)(m0 + wm * 64 + (lane >> 2));
    #pragma unroll
    for (int nf = 0; nf < 4; nf++) {
        const int n = n0 + wn * 32 + nf * 8 + ncol;
        if (n >= V_) continue;
        const float2 bv = *(const float2*)(fcb + n);
        #pragma unroll
        for (int mf = 0; mf < 4; mf++) {
            float* cp = C + (rbase + (size_t)mf * 16) * V_ + n;
            float2 o0 = make_float2(acc[mf][nf][0] + bv.x, acc[mf][nf][1] + bv.y);
            float2 o1 = make_float2(acc[mf][nf][2] + bv.x, acc[mf][nf][3] + bv.y);
            *(float2*)cp                    = o0;
            *(float2*)(cp + (size_t)8 * V_) = o1;
        }
    }
}

// ---------------------------------------------------------------------------
extern "C" void kernel_launch(void* const* d_in, const int* in_sizes, int n_in,
                              void* d_out, int out_size)
{
    const int*   x     = (const int*)  d_in[0];
    const float* emb   = (const float*)d_in[1];
    const float* W_ih0 = (const float*)d_in[2];
    const float* W_hh0 = (const float*)d_in[3];
    const float* b_ih0 = (const float*)d_in[4];
    const float* b_hh0 = (const float*)d_in[5];
    const float* W_ih1 = (const float*)d_in[6];
    const float* W_hh1 = (const float*)d_in[7];
    const float* b_ih1 = (const float*)d_in[8];
    const float* b_hh1 = (const float*)d_in[9];
    const float* fc_w  = (const float*)d_in[10];
    const float* fc_b  = (const float*)d_in[11];
    float* out = (float*)d_out;

    float *xp, *y0;
    __nv_bfloat16 *Whi, *Wlo, *Ahi, *Alo;
    cudaGetSymbolAddress((void**)&xp, g_xp);
    cudaGetSymbolAddress((void**)&y0, g_y0);
    cudaGetSymbolAddress((void**)&Whi, g_Whi);
    cudaGetSymbolAddress((void**)&Wlo, g_Wlo);
    cudaGetSymbolAddress((void**)&Ahi, g_Ahi);
    cudaGetSymbolAddress((void**)&Alo, g_Alo);

    cudaFuncSetAttribute(fc_mma_kernel, cudaFuncAttributeMaxDynamicSharedMemorySize, FC_SMEM);

    float* hc = out + (size_t)M_ * V_;   // logits, then h[2,B,H], c[2,B,H]

    // convert fc_w to bf16 hi/lo
    {
        int n4 = (V_ * H_) / 4;
        cvt_hilo<<<(n4 + 255) / 256, 256>>>((const float4*)fc_w, (ushort4*)Whi, (ushort4*)Wlo, n4);
    }

    // Layer 0 (writes y0 as float)
    proj_kernel<true><<<dim3(G_/64, M_/64), 256>>>(nullptr, x, emb, W_ih0, b_ih0, b_hh0, xp);
    lstm_kernel<<<2 * B_, 256>>>(xp, W_hh0, y0, nullptr, nullptr, hc, 0, 0);

    // Layer 1 (writes Ahi/Alo directly — hi/lo split fused into epilogue)
    proj_kernel<false><<<dim3(G_/64, M_/64), 256>>>(y0, nullptr, nullptr, W_ih1, b_ih1, b_hh1, xp);
    lstm_kernel<<<2 * B_, 256>>>(xp, W_hh1, nullptr, Ahi, Alo, hc, 1, 1);

    // Vocab projection on tensor cores (HMMA via mma.sync)
    fc_mma_kernel<<<dim3((V_ + 127) / 128, M_ / 128), 256, FC_SMEM>>>(Ahi, Alo, Whi, Wlo, fc_b, out);
}

// round 13
// speedup vs baseline: 1.1903x; 1.1279x over previous
#include <cuda_runtime.h>
#include <cuda_bf16.h>
#include <cstdint>

#define B_ 16
#define T_ 256
#define H_ 128
#define E_ 128
#define V_ 50000
#define G_ 512          // 4*H
#define M_ 4096         // B*T

typedef unsigned long long ull;

// ---------------- scratch (no cudaMalloc allowed) ----------------
__device__ float g_xp[M_ * G_];        // layer-0 input projection
__device__ float g_xp1[M_ * G_];       // layer-1 input projection (pipeline stage P1)
__device__ float g_y0[M_ * H_];
__device__ __nv_bfloat16 g_Whi[(size_t)V_ * H_];
__device__ __nv_bfloat16 g_Wlo[(size_t)V_ * H_];
__device__ __nv_bfloat16 g_Ahi[M_ * H_];
__device__ __nv_bfloat16 g_Alo[M_ * H_];
__device__ unsigned g_flags0[B_];      // steps of layer-0 completed per batch
__device__ unsigned g_flags1[2 * B_];  // steps of proj-1 completed per (batch, half)

// ---------------- f32x2 helpers ----------------
__device__ __forceinline__ ull fma2(ull a, ull b, ull c) {
    ull d; asm("fma.rn.f32x2 %0, %1, %2, %3;" : "=l"(d) : "l"(a), "l"(b), "l"(c)); return d;
}
__device__ __forceinline__ ull add2(ull a, ull b) {
    ull d; asm("add.rn.f32x2 %0, %1, %2;" : "=l"(d) : "l"(a), "l"(b)); return d;
}
__device__ __forceinline__ float2 unpack2(ull v) {
    float2 r; asm("mov.b64 {%0, %1}, %2;" : "=f"(r.x), "=f"(r.y) : "l"(v)); return r;
}

// ---------------- misc helpers ----------------
__device__ __forceinline__ uint32_t smem_u32(const void* p) {
    uint32_t a;
    asm("{ .reg .u64 t; cvta.to.shared.u64 t, %1; cvt.u32.u64 %0, t; }" : "=r"(a) : "l"(p));
    return a;
}
__device__ __forceinline__ void cpasync16(uint32_t dst, const void* src) {
    asm volatile("cp.async.cg.shared.global [%0], [%1], 16;" :: "r"(dst), "l"(src));
}
#define CP_COMMIT() asm volatile("cp.async.commit_group;" ::: "memory")
#define CP_WAIT(n)  asm volatile("cp.async.wait_group %0;" :: "n"(n) : "memory")

__device__ __forceinline__ void ldsm_x4(uint32_t& r0, uint32_t& r1, uint32_t& r2, uint32_t& r3,
                                        uint32_t addr) {
    asm volatile("ldmatrix.sync.aligned.m8n8.x4.shared.b16 {%0,%1,%2,%3}, [%4];"
                 : "=r"(r0), "=r"(r1), "=r"(r2), "=r"(r3) : "r"(addr));
}
__device__ __forceinline__ void mma_bf16(float* c, const uint32_t* a, const uint32_t* b) {
    asm volatile(
        "mma.sync.aligned.m16n8k16.row.col.f32.bf16.bf16.f32 "
        "{%0,%1,%2,%3}, {%4,%5,%6,%7}, {%8,%9}, {%0,%1,%2,%3};"
        : "+f"(c[0]), "+f"(c[1]), "+f"(c[2]), "+f"(c[3])
        : "r"(a[0]), "r"(a[1]), "r"(a[2]), "r"(a[3]), "r"(b[0]), "r"(b[1]));
}

// inter-stage flag protocol (single writer thread per flag word)
__device__ __forceinline__ void poll_ge(const unsigned* p, unsigned tgt) {
    unsigned v;
    do {
        asm volatile("ld.acquire.gpu.global.u32 %0, [%1];" : "=r"(v) : "l"(p) : "memory");
    } while (v < tgt);
}
__device__ __forceinline__ void publish(unsigned* p, unsigned v) {
    __threadfence();   // cumulative: orders all CTA writes observed via prior __syncthreads
    asm volatile("st.relaxed.gpu.global.u32 [%0], %1;" :: "l"(p), "r"(v) : "memory");
}

// ---------------------------------------------------------------------------
// flag reset (runs each launch / graph replay, before the pipeline kernel)
// ---------------------------------------------------------------------------
__global__ void zero_flags()
{
    int i = threadIdx.x;
    if (i < B_) g_flags0[i] = 0;
    if (i < 2 * B_) g_flags1[i] = 0;
}

// ---------------------------------------------------------------------------
// hi/lo bf16 split conversion (vectorized x4) — fc_w only
// ---------------------------------------------------------------------------
__global__ __launch_bounds__(256)
void cvt_hilo(const float4* __restrict__ src, ushort4* __restrict__ hi,
              ushort4* __restrict__ lo, int n4)
{
    int i = blockIdx.x * 256 + threadIdx.x;
    if (i >= n4) return;
    float4 v = src[i];
    ushort4 h, l;
    {
        __nv_bfloat16 hb;
        hb = __float2bfloat16(v.x); h.x = __bfloat16_as_ushort(hb);
        l.x = __bfloat16_as_ushort(__float2bfloat16(v.x - __bfloat162float(hb)));
        hb = __float2bfloat16(v.y); h.y = __bfloat16_as_ushort(hb);
        l.y = __bfloat16_as_ushort(__float2bfloat16(v.y - __bfloat162float(hb)));
        hb = __float2bfloat16(v.z); h.z = __bfloat16_as_ushort(hb);
        l.z = __bfloat16_as_ushort(__float2bfloat16(v.z - __bfloat162float(hb)));
        hb = __float2bfloat16(v.w); h.w = __bfloat16_as_ushort(hb);
        l.w = __bfloat16_as_ushort(__float2bfloat16(v.w - __bfloat162float(hb)));
    }
    hi[i] = h;
    lo[i] = l;
}

// ---------------------------------------------------------------------------
// Projection GEMM (layer-0 input only): C[M_,512] = emb[x] @ W^T + bias
// ---------------------------------------------------------------------------
__global__ __launch_bounds__(256)
void proj_kernel(const int* __restrict__ xidx, const float* __restrict__ emb,
                 const float* __restrict__ W,
                 const float* __restrict__ bia, const float* __restrict__ bib,
                 float* __restrict__ C)
{
    __shared__ float As[64][64];
    __shared__ float Bs[64][64];
    const int tid = threadIdx.x;
    const int tx = tid & 15, ty = tid >> 4;
    const int m0 = blockIdx.y * 64, n0 = blockIdx.x * 64;
    const int l  = tid & 63;
    const int kq = tid >> 6;

    const float* arow = emb + (size_t)xidx[m0 + l] * E_;
    const float* brow = W + (size_t)(n0 + l) * H_;

    float acc[4][4] = {};
    for (int kc = 0; kc < 128; kc += 64) {
        __syncthreads();
        #pragma unroll
        for (int it = 0; it < 4; it++) {
            int kb = kq * 4 + it * 16;
            float4 va = *(const float4*)(arow + kc + kb);
            As[kb+0][l] = va.x; As[kb+1][l] = va.y; As[kb+2][l] = va.z; As[kb+3][l] = va.w;
            float4 vb = *(const float4*)(brow + kc + kb);
            Bs[kb+0][l] = vb.x; Bs[kb+1][l] = vb.y; Bs[kb+2][l] = vb.z; Bs[kb+3][l] = vb.w;
        }
        __syncthreads();
        #pragma unroll 16
        for (int k = 0; k < 64; k++) {
            float4 a4 = *(const float4*)&As[k][ty * 4];
            float4 b4 = *(const float4*)&Bs[k][tx * 4];
            float av[4] = {a4.x, a4.y, a4.z, a4.w};
            float bv[4] = {b4.x, b4.y, b4.z, b4.w};
            #pragma unroll
            for (int i = 0; i < 4; i++)
                #pragma unroll
                for (int j = 0; j < 4; j++)
                    acc[i][j] = fmaf(av[i], bv[j], acc[i][j]);
        }
    }
    #pragma unroll
    for (int i = 0; i < 4; i++) {
        int m = m0 + ty * 4 + i;
        #pragma unroll
        for (int j = 0; j < 4; j++) {
            int n = n0 + tx * 4 + j;
            C[(size_t)m * G_ + n] = acc[i][j] + bia[n] + bib[n];
        }
    }
}

// ---------------------------------------------------------------------------
// 3-stage recurrent pipeline in ONE kernel (96 CTAs, single wave):
//   blocks  0-31: L0  = layer-0 LSTM (16 2-CTA clusters, R11 recurrence)
//                  per step publishes flags0[b] = t+1 after writing y0_t.
//   blocks 32-63: P1  = layer-1 input projection, W_ih1 rows in registers;
//                  polls flags0, produces xp1_t, publishes flags1[2b+r].
//   blocks 64-95: L1  = layer-1 LSTM; polls flags1, reads xp1_t (coherent ld),
//                  fused bf16 hi/lo output epilogue (feeds FC).
// Inter-stage sync: monotonic counters + threadfence/acquire (canonical
// inter-block handoff). Intra-pair sync: barrier.cluster (proven R9/R11).
// ---------------------------------------------------------------------------
__global__ __launch_bounds__(256, 1) __cluster_dims__(2, 1, 1)
void pipeline_kernel(const float* __restrict__ xp0, float* y0, float* xp1,
                     const float* __restrict__ Whh0, const float* __restrict__ Wih1,
                     const float* __restrict__ Whh1,
                     const float* __restrict__ bi1, const float* __restrict__ bh1,
                     __nv_bfloat16* __restrict__ yhi, __nv_bfloat16* __restrict__ ylo,
                     float* __restrict__ hc_out)
{
    __shared__ float sh[H_ + 2 * G_];   // lstm: h_s[128] + act[2][512]; P1: ys[128]

    const int tid  = threadIdx.x;
    const int role = blockIdx.x >> 5;   // 0=L0, 1=P1, 2=L1

    if (role == 1) {
        // ---------------- P1: layer-1 input projection ----------------
        float* ys = sh;
        const int idx = blockIdx.x - 32;        // 0..31
        const int b   = idx >> 1;
        const int r   = idx & 1;
        const int g   = r * 256 + tid;          // gate row 0..511

        ull w2[64];
        {
            const ulonglong2* wp = (const ulonglong2*)(Wih1 + (size_t)g * H_);
            #pragma unroll
            for (int i = 0; i < 32; i++) { ulonglong2 v = wp[i]; w2[2*i] = v.x; w2[2*i+1] = v.y; }
        }
        const float breg = bi1[g] + bh1[g];

        for (int t = 0; t < T_; t++) {
            poll_ge(&g_flags0[b], (unsigned)(t + 1));
            if (tid < 32) {   // 32 x float4 = 128 floats (coherent load; y0 just released)
                float4 v = *(const float4*)(y0 + ((size_t)b * T_ + t) * H_ + tid * 4);
                *(float4*)&ys[tid * 4] = v;
            }
            __syncthreads();

            ull a0 = 0, a1 = 0, a2 = 0, a3 = 0;
            const ulonglong2* hp = (const ulonglong2*)ys;
            #pragma unroll
            for (int i = 0; i < 32; i++) {
                ulonglong2 hv = hp[i];
                if (i & 1) { a2 = fma2(w2[2*i], hv.x, a2); a3 = fma2(w2[2*i+1], hv.y, a3); }
                else       { a0 = fma2(w2[2*i], hv.x, a0); a1 = fma2(w2[2*i+1], hv.y, a1); }
            }
            a0 = add2(a0, a2); a1 = add2(a1, a3); a0 = add2(a0, a1);
            float2 pr = unpack2(a0);
            xp1[((size_t)b * T_ + t) * G_ + g] = pr.x + pr.y + breg;

            __syncthreads();                    // all STG issued; ys reusable
            if (tid == 0) publish(&g_flags1[idx], (unsigned)(t + 1));
        }
        return;
    }

    // ---------------- L0 / L1: LSTM recurrence (R11 design) ----------------
    const bool isL0 = (role == 0);
    float* h_s = sh;
    float* act = sh + H_;                       // act[2][G_] flattened

    uint32_t rank; asm("mov.u32 %0, %%cluster_ctarank;" : "=r"(rank));
    const int b  = (blockIdx.x & 31) >> 1;
    const int gG = (int)rank * 256 + tid;       // global gate row 0..511
    const int gtype = gG >> 7;                  // 0:i 1:f 2:g~ 3:o

    const float* Whh = isL0 ? Whh0 : Whh1;
    ull w2[64];
    {
        const ulonglong2* wp = (const ulonglong2*)(Whh + (size_t)gG * H_);
        #pragma unroll
        for (int i = 0; i < 32; i++) { ulonglong2 v = wp[i]; w2[2*i] = v.x; w2[2*i+1] = v.y; }
    }

    // peer addresses for this thread's act slot (both parity buffers)
    const uint32_t peer = rank ^ 1u;
    uint32_t ra0, ra1;
    {
        uint32_t la0 = smem_u32(&act[0 * G_ + gG]);
        uint32_t la1 = smem_u32(&act[1 * G_ + gG]);
        asm("mapa.shared::cluster.u32 %0, %1, %2;" : "=r"(ra0) : "r"(la0), "r"(peer));
        asm("mapa.shared::cluster.u32 %0, %1, %2;" : "=r"(ra1) : "r"(la1), "r"(peer));
    }

    float c = 0.f;
    if (tid < H_) h_s[tid] = 0.f;
    __syncthreads();                            // h_s init (local readers only)

    unsigned* myflag1 = &g_flags1[b * 2 + (int)rank];

    for (int t = 0; t < T_; t++) {
        float xv;
        if (isL0) {
            xv = __ldg(xp0 + ((size_t)b * T_ + t) * G_ + gG);
        } else {
            poll_ge(myflag1, (unsigned)(t + 1));
            xv = xp1[((size_t)b * T_ + t) * G_ + gG];   // coherent load after acquire
        }

        // dot: h_s (broadcast LDS) x W-row (registers), 4 independent chains
        ull a0 = 0, a1 = 0, a2 = 0, a3 = 0;
        const ulonglong2* hp = (const ulonglong2*)h_s;
        #pragma unroll
        for (int i = 0; i < 32; i++) {
            ulonglong2 hv = hp[i];
            if (i & 1) { a2 = fma2(w2[2*i], hv.x, a2); a3 = fma2(w2[2*i+1], hv.y, a3); }
            else       { a0 = fma2(w2[2*i], hv.x, a0); a1 = fma2(w2[2*i+1], hv.y, a1); }
        }
        a0 = add2(a0, a2); a1 = add2(a1, a3); a0 = add2(a0, a1);
        float2 pr = unpack2(a0);
        float raw = pr.x + pr.y + xv;

        float a = (gtype == 2) ? tanhf(raw) : (1.0f / (1.0f + __expf(-raw)));

        const int p = t & 1;
        act[p * G_ + gG] = a;                         // local copy
        asm volatile("st.shared::cluster.f32 [%0], %1;"
                     :: "r"(p ? ra1 : ra0), "f"(a));  // peer copy

        asm volatile("barrier.cluster.arrive.aligned;" ::: "memory");
        asm volatile("barrier.cluster.wait.aligned;"   ::: "memory");

        if (tid < H_) {                               // redundant in both CTAs
            float iv = act[p * G_ + tid];
            float fv = act[p * G_ + H_ + tid];
            float gv = act[p * G_ + 2 * H_ + tid];
            float ov = act[p * G_ + 3 * H_ + tid];
            c = fv * c + iv * gv;
            float hnew = ov * tanhf(c);
            h_s[tid] = hnew;
            if (rank == 0) {
                const size_t row = (size_t)b * T_ + t;
                if (isL0) {
                    y0[row * H_ + tid] = hnew;
                } else {
                    __nv_bfloat16 hb = __float2bfloat16(hnew);
                    yhi[row * H_ + tid] = hb;
                    ylo[row * H_ + tid] = __float2bfloat16(hnew - __bfloat162float(hb));
                }
            }
        }
        __syncthreads();                              // h_s ready; y0 writes visible CTA-wide
        if (isL0 && rank == 0 && tid == 0)
            publish(&g_flags0[b], (unsigned)(t + 1));
    }

    if (rank == 0 && tid < H_) {
        const int layer = isL0 ? 0 : 1;
        hc_out[(size_t)layer * (B_ * H_) + b * H_ + tid]       = h_s[tid];
        hc_out[(size_t)(2 + layer) * (B_ * H_) + b * H_ + tid] = c;
    }
}

// ---------------------------------------------------------------------------
// FC head via mma.sync (HMMA): logits = y1 @ fc_w^T + fc_b
// hi/lo bf16 split: acc = Ahi*Whi + Ahi*Wlo + Alo*Whi  (virtual K = 384)
// R11 B-step grouping: 4 resident A tiles, 4 B loads, 4 sync pairs.
// ---------------------------------------------------------------------------
#define FC_PAD    72                        // row stride in bf16 elems
#define FC_TILE   (128 * FC_PAD * 2)        // 18432 bytes per 128x64 tile
#define FC_BBASE  (4 * FC_TILE)             // B region offset
#define FC_SMEM   (FC_BBASE + 2 * FC_TILE)  // 110592

__device__ __forceinline__ void fc_load_A(uint32_t dst,
    const __nv_bfloat16* __restrict__ src, int m0, int koff, int tid)
{
    #pragma unroll
    for (int it = 0; it < 4; it++) {
        int idx = tid + it * 256;
        int row = idx >> 3, c8 = idx & 7;
        cpasync16(dst + (uint32_t)(row * FC_PAD + c8 * 8) * 2,
                  src + (size_t)(m0 + row) * H_ + koff + c8 * 8);
    }
}
__device__ __forceinline__ void fc_load_B(uint32_t dst,
    const __nv_bfloat16* __restrict__ src, int n0, int koff, int tid)
{
    #pragma unroll
    for (int it = 0; it < 4; it++) {
        int idx = tid + it * 256;
        int row = idx >> 3, c8 = idx & 7;
        int gn = n0 + row; if (gn >= V_) gn = V_ - 1;   // clamp; never stored
        cpasync16(dst + (uint32_t)(row * FC_PAD + c8 * 8) * 2,
                  src + (size_t)gn * H_ + koff + c8 * 8);
    }
}

__global__ __launch_bounds__(256, 2)
void fc_mma_kernel(const __nv_bfloat16* __restrict__ Ahi, const __nv_bfloat16* __restrict__ Alo,
                   const __nv_bfloat16* __restrict__ Whi, const __nv_bfloat16* __restrict__ Wlo,
                   const float* __restrict__ fcb, float* __restrict__ C)
{
    extern __shared__ char smem[];
    const uint32_t sbase = smem_u32(smem);
    const int tid  = threadIdx.x;
    const int wid  = tid >> 5, lane = tid & 31;
    const int wm   = wid >> 2;
    const int wn   = wid & 3;
    const int n0   = blockIdx.x * 128;
    const int m0   = blockIdx.y * 128;

    const uint32_t aRel = (uint32_t)(((wm * 64 + (lane & 15)) * FC_PAD + (lane >> 4) * 8) * 2);
    const uint32_t bRel = (uint32_t)(
        ((wn * 32 + (lane >> 4) * 8 + (lane & 7)) * FC_PAD + ((lane >> 3) & 1) * 8) * 2);

    float acc[4][4][4];
    #pragma unroll
    for (int i = 0; i < 4; i++)
        #pragma unroll
        for (int j = 0; j < 4; j++)
            #pragma unroll
            for (int k = 0; k < 4; k++) acc[i][j][k] = 0.f;

    fc_load_A(sbase + 0 * FC_TILE, Ahi, m0, 0,  tid);
    fc_load_A(sbase + 1 * FC_TILE, Ahi, m0, 64, tid);
    fc_load_A(sbase + 2 * FC_TILE, Alo, m0, 0,  tid);
    fc_load_A(sbase + 3 * FC_TILE, Alo, m0, 64, tid);
    fc_load_B(sbase + FC_BBASE + 0 * FC_TILE, Whi, n0, 0, tid);
    CP_COMMIT();                                        // G0 = {A x4, B0}
    fc_load_B(sbase + FC_BBASE + 1 * FC_TILE, Whi, n0, 64, tid);
    CP_COMMIT();                                        // G1 = {B1}

    #pragma unroll
    for (int s = 0; s < 4; s++) {
        const int At0[4] = {0, 1, 0, 1};
        const int At1[4] = {2, 3, -1, -1};
        if (s < 3) { CP_WAIT(1); } else { CP_WAIT(0); }
        __syncthreads();

        const uint32_t bB = sbase + FC_BBASE + (uint32_t)(s & 1) * FC_TILE + bRel;
        #pragma unroll
        for (int k16 = 0; k16 < 4; k16++) {
            uint32_t b[4][2];
            #pragma unroll
            for (int np = 0; np < 2; np++)
                ldsm_x4(b[2*np][0], b[2*np][1], b[2*np+1][0], b[2*np+1][1],
                        bB + np * (16 * FC_PAD * 2) + k16 * 32);
            {
                const uint32_t aB = sbase + (uint32_t)At0[s] * FC_TILE + aRel;
                uint32_t a[4][4];
                #pragma unroll
                for (int mf = 0; mf < 4; mf++)
                    ldsm_x4(a[mf][0], a[mf][1], a[mf][2], a[mf][3],
                            aB + mf * (16 * FC_PAD * 2) + k16 * 32);
                #pragma unroll
                for (int mf = 0; mf < 4; mf++)
                    #pragma unroll
                    for (int nf = 0; nf < 4; nf++)
                        mma_bf16(acc[mf][nf], a[mf], b[nf]);
            }
            if (s < 2) {
                const uint32_t aB = sbase + (uint32_t)At1[s] * FC_TILE + aRel;
                uint32_t a[4][4];
                #pragma unroll
                for (int mf = 0; mf < 4; mf++)
                    ldsm_x4(a[mf][0], a[mf][1], a[mf][2], a[mf][3],
                            aB + mf * (16 * FC_PAD * 2) + k16 * 32);
                #pragma unroll
                for (int mf = 0; mf < 4; mf++)
                    #pragma unroll
                    for (int nf = 0; nf < 4; nf++)
                        mma_bf16(acc[mf][nf], a[mf], b[nf]);
            }
        }
        __syncthreads();

        if (s + 2 <= 3) {
            const int Bk = (s & 1) * 64;
            fc_load_B(sbase + FC_BBASE + (uint32_t)(s & 1) * FC_TILE, Wlo, n0, Bk, tid);
            CP_COMMIT();
        }
    }

    const int ncol = 2 * (lane & 3);
    const size_t rbase = (size_t)(m0 + wm * 64 + (lane >> 2));
    #pragma unroll
    for (int nf = 0; nf < 4; nf++) {
        const int n = n0 + wn * 32 + nf * 8 + ncol;
        if (n >= V_) continue;
        const float2 bv = *(const float2*)(fcb + n);
        #pragma unroll
        for (int mf = 0; mf < 4; mf++) {
            float* cp = C + (rbase + (size_t)mf * 16) * V_ + n;
            float2 o0 = make_float2(acc[mf][nf][0] + bv.x, acc[mf][nf][1] + bv.y);
            float2 o1 = make_float2(acc[mf][nf][2] + bv.x, acc[mf][nf][3] + bv.y);
            *(float2*)cp                    = o0;
            *(float2*)(cp + (size_t)8 * V_) = o1;
        }
    }
}

// ---------------------------------------------------------------------------
extern "C" void kernel_launch(void* const* d_in, const int* in_sizes, int n_in,
                              void* d_out, int out_size)
{
    const int*   x     = (const int*)  d_in[0];
    const float* emb   = (const float*)d_in[1];
    const float* W_ih0 = (const float*)d_in[2];
    const float* W_hh0 = (const float*)d_in[3];
    const float* b_ih0 = (const float*)d_in[4];
    const float* b_hh0 = (const float*)d_in[5];
    const float* W_ih1 = (const float*)d_in[6];
    const float* W_hh1 = (const float*)d_in[7];
    const float* b_ih1 = (const float*)d_in[8];
    const float* b_hh1 = (const float*)d_in[9];
    const float* fc_w  = (const float*)d_in[10];
    const float* fc_b  = (const float*)d_in[11];
    float* out = (float*)d_out;

    float *xp, *xp1, *y0;
    __nv_bfloat16 *Whi, *Wlo, *Ahi, *Alo;
    cudaGetSymbolAddress((void**)&xp,  g_xp);
    cudaGetSymbolAddress((void**)&xp1, g_xp1);
    cudaGetSymbolAddress((void**)&y0,  g_y0);
    cudaGetSymbolAddress((void**)&Whi, g_Whi);
    cudaGetSymbolAddress((void**)&Wlo, g_Wlo);
    cudaGetSymbolAddress((void**)&Ahi, g_Ahi);
    cudaGetSymbolAddress((void**)&Alo, g_Alo);

    cudaFuncSetAttribute(fc_mma_kernel, cudaFuncAttributeMaxDynamicSharedMemorySize, FC_SMEM);

    float* hc = out + (size_t)M_ * V_;   // logits, then h[2,B,H], c[2,B,H]

    // convert fc_w to bf16 hi/lo
    {
        int n4 = (V_ * H_) / 4;
        cvt_hilo<<<(n4 + 255) / 256, 256>>>((const float4*)fc_w, (ushort4*)Whi, (ushort4*)Wlo, n4);
    }

    // layer-0 input projection (embedding gather fused)
    proj_kernel<<<dim3(G_/64, M_/64), 256>>>(x, emb, W_ih0, b_ih0, b_hh0, xp);

    // reset inter-stage flags (every launch / graph replay)
    zero_flags<<<1, 64>>>();

    // 3-stage recurrent pipeline: L0 | P1 | L1 (96 CTAs, one wave)
    pipeline_kernel<<<96, 256>>>(xp, y0, xp1, W_hh0, W_ih1, W_hh1,
                                 b_ih1, b_hh1, Ahi, Alo, hc);

    // Vocab projection on tensor cores (HMMA via mma.sync)
    fc_mma_kernel<<<dim3((V_ + 127) / 128, M_ / 128), 256, FC_SMEM>>>(Ahi, Alo, Whi, Wlo, fc_b, out);
}